// round 5
// baseline (speedup 1.0000x reference)
#include <cuda_runtime.h>
#include <cstdint>
#include <math.h>

// ---------------------------------------------------------------- constants
constexpr int Bz   = 4;
constexpr int Lseq = 4096;
constexpr int Dm   = 2048;
constexpr int Mtot = Bz * Lseq;                 // 16384
constexpr float SCALE = 0.08838834764831845f;   // 128^-0.5

constexpr int NC = 64;                          // scan chunks
constexpr int CH = Lseq / NC;                   // 64

// GEMM tiling: CTA 128x128, 4 warps of 64x64, BK=32, 3-stage cp.async, 2 CTA/SM
constexpr int BM = 128, BN = 128, BK = 32;
constexpr int STAGES = 3;
constexpr int KT = Dm / BK;                       // 64
constexpr int ROWF = 36;                          // padded row stride (floats)
constexpr int A_TILE = BM * ROWF * 4;             // 18432
constexpr int B_TILE = BN * ROWF * 4;             // 18432
constexpr int STAGE_BYTES = A_TILE + B_TILE;      // 36864
constexpr int SMEM_TOTAL  = STAGES * STAGE_BYTES; // 110592

// ---------------------------------------------------------------- scratch
__device__ float g_phiq[(size_t)Mtot * Dm];
__device__ float g_phik[(size_t)Mtot * Dm];
__device__ float g_v   [(size_t)Mtot * Dm];
__device__ float g_ctx [(size_t)Mtot * Dm];
__device__ float g_part[(size_t)Bz * NC * Dm];

// ---------------------------------------------------------------- helpers
__device__ __forceinline__ uint32_t smem_u32(const void* p) {
    uint32_t a;
    asm("{ .reg .u64 t; cvta.to.shared.u64 t, %1; cvt.u32.u64 %0, t; }"
        : "=r"(a) : "l"(p));
    return a;
}
__device__ __forceinline__ void cp16(uint32_t dst, const void* src) {
    asm volatile("cp.async.cg.shared.global [%0], [%1], 16;"
                 :: "r"(dst), "l"(src) : "memory");
}
__device__ __forceinline__ void mma_tf32(float* d, const uint32_t* a,
                                         const uint32_t* b) {
    asm volatile(
        "mma.sync.aligned.m16n8k8.row.col.f32.tf32.tf32.f32 "
        "{%0,%1,%2,%3}, {%4,%5,%6,%7}, {%8,%9}, {%0,%1,%2,%3};"
        : "+f"(d[0]), "+f"(d[1]), "+f"(d[2]), "+f"(d[3])
        : "r"(a[0]), "r"(a[1]), "r"(a[2]), "r"(a[3]), "r"(b[0]), "r"(b[1]));
}
// load float from smem and round-to-nearest tf32 in-register
__device__ __forceinline__ uint32_t ld_rtf32(const float* p) {
    uint32_t u;
    asm("cvt.rna.tf32.f32 %0, %1;" : "=r"(u) : "f"(*p));
    return u;
}

// ------------------------------------------------------------------- GEMM
// C[M][N] = act(A[M][K] @ W[N][K]^T + bias[N]); fp32 in, tf32-rounded in-reg.
template<int ACT>
__global__ void __launch_bounds__(128, 2)
gemm_mma(const float* __restrict__ A, const float* __restrict__ W,
         const float* __restrict__ bias, float* __restrict__ C)
{
    extern __shared__ float smem[];
    const uint32_t sb = smem_u32(smem);
    const int tid  = threadIdx.x;
    const int wid  = tid >> 5;
    const int lane = tid & 31;
    const int wm = wid & 1;             // 0..1  -> 64-row slab
    const int wn = wid >> 1;            // 0..1  -> 64-col slab
    const int gq = lane >> 2;           // 0..7
    const int gr = lane & 3;            // 0..3
    const int m0 = blockIdx.y * BM;
    const int n0 = blockIdx.x * BN;

    float acc[4][8][4];
#pragma unroll
    for (int i = 0; i < 4; i++)
#pragma unroll
        for (int j = 0; j < 8; j++)
#pragma unroll
            for (int k = 0; k < 4; k++) acc[i][j][k] = 0.f;

    auto issue = [&](int kt) {
        const int s = kt % STAGES;
        const uint32_t dA = sb + s * STAGE_BYTES;
        const uint32_t dB = dA + A_TILE;
        const float* Ag = A + (size_t)m0 * Dm + kt * BK;
        const float* Wg = W + (size_t)n0 * Dm + kt * BK;
#pragma unroll
        for (int i = 0; i < 8; i++) {       // 128 rows x 8 chunks
            int ch = tid + 128 * i, row = ch >> 3, c4 = ch & 7;
            cp16(dA + row * 144 + c4 * 16, Ag + (size_t)row * Dm + c4 * 4);
        }
#pragma unroll
        for (int i = 0; i < 8; i++) {
            int ch = tid + 128 * i, row = ch >> 3, c4 = ch & 7;
            cp16(dB + row * 144 + c4 * 16, Wg + (size_t)row * Dm + c4 * 4);
        }
        asm volatile("cp.async.commit_group;" ::: "memory");
    };

    issue(0);
    issue(1);

    for (int kt = 0; kt < KT; kt++) {
        const int s = kt % STAGES;
        asm volatile("cp.async.wait_group 1;" ::: "memory");
        __syncthreads();

        if (kt + 2 < KT) issue(kt + 2);
        else asm volatile("cp.async.commit_group;" ::: "memory");

        const float* fA = smem + (size_t)s * STAGE_BYTES / 4;
        const float* fB = fA + A_TILE / 4;

#pragma unroll
        for (int ks = 0; ks < 4; ks++) {
            const int k0 = ks * 8;
            uint32_t af[4][4], bf[8][2];
#pragma unroll
            for (int mt = 0; mt < 4; mt++) {
                const int r = wm * 64 + mt * 16 + gq;
                af[mt][0] = ld_rtf32(&fA[(size_t)r       * ROWF + k0 + gr]);
                af[mt][1] = ld_rtf32(&fA[(size_t)(r + 8) * ROWF + k0 + gr]);
                af[mt][2] = ld_rtf32(&fA[(size_t)r       * ROWF + k0 + gr + 4]);
                af[mt][3] = ld_rtf32(&fA[(size_t)(r + 8) * ROWF + k0 + gr + 4]);
            }
#pragma unroll
            for (int nt = 0; nt < 8; nt++) {
                const int n = wn * 64 + nt * 8 + gq;
                bf[nt][0] = ld_rtf32(&fB[(size_t)n * ROWF + k0 + gr]);
                bf[nt][1] = ld_rtf32(&fB[(size_t)n * ROWF + k0 + gr + 4]);
            }
#pragma unroll
            for (int mt = 0; mt < 4; mt++)
#pragma unroll
                for (int nt = 0; nt < 8; nt++)
                    mma_tf32(acc[mt][nt], af[mt], bf[nt]);
        }
    }

    // ----------------------------- epilogue --------------------------------
#pragma unroll
    for (int mt = 0; mt < 4; mt++) {
        const int r0 = m0 + wm * 64 + mt * 16 + gq;
#pragma unroll
        for (int nt = 0; nt < 8; nt++) {
            const int c0 = n0 + wn * 64 + nt * 8 + gr * 2;
            float b0 = bias[c0], b1 = bias[c0 + 1];
            float v0 = acc[mt][nt][0] + b0;
            float v1 = acc[mt][nt][1] + b1;
            float v2 = acc[mt][nt][2] + b0;
            float v3 = acc[mt][nt][3] + b1;
            if (ACT) {
                v0 = (v0 > 0.f) ? (v0 + 1.f) : expf(v0);
                v1 = (v1 > 0.f) ? (v1 + 1.f) : expf(v1);
                v2 = (v2 > 0.f) ? (v2 + 1.f) : expf(v2);
                v3 = (v3 > 0.f) ? (v3 + 1.f) : expf(v3);
            }
            *(float2*)(C + (size_t)r0 * Dm + c0)       = make_float2(v0, v1);
            *(float2*)(C + (size_t)(r0 + 8) * Dm + c0) = make_float2(v2, v3);
        }
    }
}

// ---------------------------------------------------------------- scan stage
__global__ void chunk_partial(const float* __restrict__ pk,
                              const float* __restrict__ pv,
                              float* __restrict__ part)
{
    const int d = blockIdx.x * 256 + threadIdx.x;
    const int c = blockIdx.y;
    const int b = blockIdx.z;
    size_t base = ((size_t)b * Lseq + (size_t)c * CH) * Dm + d;
    float s = 0.f;
#pragma unroll 4
    for (int i = 0; i < CH; i++) {
        size_t idx = base + (size_t)i * Dm;
        s += pk[idx] * pv[idx];
    }
    part[((size_t)b * NC + c) * Dm + d] = s;
}

__global__ void scan_partials(float* __restrict__ part)
{
    const int d = blockIdx.x * 256 + threadIdx.x;
    const int b = blockIdx.y;
    float run = 0.f;
    for (int c = 0; c < NC; c++) {
        size_t idx = ((size_t)b * NC + c) * Dm + d;
        float t = part[idx];
        part[idx] = run;
        run += t;
    }
}

__global__ void apply_scan(const float* __restrict__ pq,
                           const float* __restrict__ pk,
                           const float* __restrict__ pv,
                           const float* __restrict__ part,
                           float* __restrict__ ctx)
{
    const int d = blockIdx.x * 256 + threadIdx.x;
    const int c = blockIdx.y;
    const int b = blockIdx.z;
    float run = part[((size_t)b * NC + c) * Dm + d];
    size_t base = ((size_t)b * Lseq + (size_t)c * CH) * Dm + d;
#pragma unroll 4
    for (int i = 0; i < CH; i++) {
        size_t idx = base + (size_t)i * Dm;
        run += pk[idx] * pv[idx];
        ctx[idx] = pq[idx] * run * SCALE;
    }
}

// ---------------------------------------------------------------- launch
extern "C" void kernel_launch(void* const* d_in, const int* in_sizes, int n_in,
                              void* d_out, int out_size)
{
    const float* x  = (const float*)d_in[0];
    const float* Wq = (const float*)d_in[1];
    const float* bq = (const float*)d_in[2];
    const float* Wk = (const float*)d_in[3];
    const float* bk = (const float*)d_in[4];
    const float* Wv = (const float*)d_in[5];
    const float* bv = (const float*)d_in[6];
    const float* Wo = (const float*)d_in[7];
    const float* bo = (const float*)d_in[8];
    float* out = (float*)d_out;

    float *phiq, *phik, *v, *ctx, *part;
    cudaGetSymbolAddress((void**)&phiq, g_phiq);
    cudaGetSymbolAddress((void**)&phik, g_phik);
    cudaGetSymbolAddress((void**)&v,    g_v);
    cudaGetSymbolAddress((void**)&ctx,  g_ctx);
    cudaGetSymbolAddress((void**)&part, g_part);

    static bool attr_set = false;
    if (!attr_set) {
        cudaFuncSetAttribute(gemm_mma<0>, cudaFuncAttributeMaxDynamicSharedMemorySize, SMEM_TOTAL);
        cudaFuncSetAttribute(gemm_mma<1>, cudaFuncAttributeMaxDynamicSharedMemorySize, SMEM_TOTAL);
        attr_set = true;
    }

    dim3 ggrid(Dm / BN, Mtot / BM);   // (16, 128)
    gemm_mma<1><<<ggrid, 128, SMEM_TOTAL>>>(x, Wq, bq, phiq);
    gemm_mma<1><<<ggrid, 128, SMEM_TOTAL>>>(x, Wk, bk, phik);
    gemm_mma<0><<<ggrid, 128, SMEM_TOTAL>>>(x, Wv, bv, v);

    dim3 pgrid(Dm / 256, NC, Bz);
    chunk_partial<<<pgrid, 256>>>(phik, v, part);
    dim3 sgrid(Dm / 256, Bz);
    scan_partials<<<sgrid, 256>>>(part);
    apply_scan<<<pgrid, 256>>>(phiq, phik, v, part, ctx);

    gemm_mma<0><<<ggrid, 128, SMEM_TOTAL>>>(ctx, Wo, bo, out);
}

// round 6
// speedup vs baseline: 1.1016x; 1.1016x over previous
#include <cuda_runtime.h>
#include <cstdint>
#include <math.h>

// ---------------------------------------------------------------- constants
constexpr int Bz   = 4;
constexpr int Lseq = 4096;
constexpr int Dm   = 2048;
constexpr int Mtot = Bz * Lseq;                 // 16384
constexpr float SCALE = 0.08838834764831845f;   // 128^-0.5

constexpr int NC = 64;                          // scan chunks
constexpr int CH = Lseq / NC;                   // 64

// GEMM tiling: CTA 128x256, 8 warps of 64x64, BK=32, 4-stage cp.async
constexpr int BM = 128, BN = 256, BK = 32;
constexpr int STAGES = 4;
constexpr int KT = Dm / BK;                       // 64
constexpr int ROWF = 36;                          // padded row stride (floats)
constexpr int A_TILE = BM * ROWF * 4;             // 18432
constexpr int B_TILE = BN * ROWF * 4;             // 36864
constexpr int STAGE_BYTES = A_TILE + B_TILE;      // 55296
constexpr int SMEM_TOTAL  = STAGES * STAGE_BYTES; // 221184

// ---------------------------------------------------------------- scratch
__device__ float g_xc  [(size_t)Mtot * Dm];
__device__ float g_wc  [4][(size_t)Dm * Dm];
__device__ float g_phiq[(size_t)Mtot * Dm];
__device__ float g_phik[(size_t)Mtot * Dm];
__device__ float g_v   [(size_t)Mtot * Dm];
__device__ float g_ctx [(size_t)Mtot * Dm];
__device__ float g_part[(size_t)Bz * NC * Dm];

// ---------------------------------------------------------------- helpers
__device__ __forceinline__ uint32_t smem_u32(const void* p) {
    uint32_t a;
    asm("{ .reg .u64 t; cvta.to.shared.u64 t, %1; cvt.u32.u64 %0, t; }"
        : "=r"(a) : "l"(p));
    return a;
}
__device__ __forceinline__ void cp16(uint32_t dst, const void* src) {
    asm volatile("cp.async.cg.shared.global [%0], [%1], 16;"
                 :: "r"(dst), "l"(src) : "memory");
}
__device__ __forceinline__ void mma_tf32(float* d, const uint32_t* a,
                                         const uint32_t* b) {
    asm volatile(
        "mma.sync.aligned.m16n8k8.row.col.f32.tf32.tf32.f32 "
        "{%0,%1,%2,%3}, {%4,%5,%6,%7}, {%8,%9}, {%0,%1,%2,%3};"
        : "+f"(d[0]), "+f"(d[1]), "+f"(d[2]), "+f"(d[3])
        : "r"(a[0]), "r"(a[1]), "r"(a[2]), "r"(a[3]), "r"(b[0]), "r"(b[1]));
}
__device__ __forceinline__ uint32_t fbits(float x) { return __float_as_uint(x); }

// ------------------------------------------------------------------- GEMM
// C[M][N] = act(A[M][K] @ W[N][K]^T + bias[N]); A,W pre-rounded to tf32.
template<int ACT>
__global__ void __launch_bounds__(256, 1)
gemm_mma(const float* __restrict__ A, const float* __restrict__ W,
         const float* __restrict__ bias, float* __restrict__ C)
{
    extern __shared__ float smem[];
    const uint32_t sb = smem_u32(smem);
    const int tid  = threadIdx.x;
    const int wid  = tid >> 5;
    const int lane = tid & 31;
    const int wm = wid & 1;             // 0..1  -> 64-row slab
    const int wn = wid >> 1;            // 0..3  -> 64-col slab
    const int gq = lane >> 2;           // 0..7
    const int gr = lane & 3;            // 0..3
    const int m0 = blockIdx.y * BM;
    const int n0 = blockIdx.x * BN;

    float acc[4][8][4];
#pragma unroll
    for (int i = 0; i < 4; i++)
#pragma unroll
        for (int j = 0; j < 8; j++)
#pragma unroll
            for (int k = 0; k < 4; k++) acc[i][j][k] = 0.f;

    auto issue = [&](int kt) {
        const int s = kt & (STAGES - 1);
        const uint32_t dA = sb + s * STAGE_BYTES;
        const uint32_t dB = dA + A_TILE;
        const float* Ag = A + (size_t)m0 * Dm + kt * BK;
        const float* Wg = W + (size_t)n0 * Dm + kt * BK;
#pragma unroll
        for (int i = 0; i < 4; i++) {       // 128 rows x 8 chunks
            int ch = tid + 256 * i, row = ch >> 3, c4 = ch & 7;
            cp16(dA + row * 144 + c4 * 16, Ag + (size_t)row * Dm + c4 * 4);
        }
#pragma unroll
        for (int i = 0; i < 8; i++) {       // 256 rows x 8 chunks
            int ch = tid + 256 * i, row = ch >> 3, c4 = ch & 7;
            cp16(dB + row * 144 + c4 * 16, Wg + (size_t)row * Dm + c4 * 4);
        }
        asm volatile("cp.async.commit_group;" ::: "memory");
    };

    issue(0);
    issue(1);
    issue(2);

    for (int kt = 0; kt < KT; kt++) {
        const int s = kt & (STAGES - 1);
        asm volatile("cp.async.wait_group 2;" ::: "memory");
        __syncthreads();

        if (kt + 3 < KT) issue(kt + 3);
        else asm volatile("cp.async.commit_group;" ::: "memory");

        const float* fA = smem + (size_t)s * STAGE_BYTES / 4;
        const float* fB = fA + A_TILE / 4;

#pragma unroll
        for (int ks = 0; ks < 4; ks++) {
            const int k0 = ks * 8;
            uint32_t af[4][4], bf[8][2];
#pragma unroll
            for (int mt = 0; mt < 4; mt++) {
                const int r = wm * 64 + mt * 16 + gq;
                af[mt][0] = fbits(fA[(size_t)r       * ROWF + k0 + gr]);
                af[mt][1] = fbits(fA[(size_t)(r + 8) * ROWF + k0 + gr]);
                af[mt][2] = fbits(fA[(size_t)r       * ROWF + k0 + gr + 4]);
                af[mt][3] = fbits(fA[(size_t)(r + 8) * ROWF + k0 + gr + 4]);
            }
#pragma unroll
            for (int nt = 0; nt < 8; nt++) {
                const int n = wn * 64 + nt * 8 + gq;
                bf[nt][0] = fbits(fB[(size_t)n * ROWF + k0 + gr]);
                bf[nt][1] = fbits(fB[(size_t)n * ROWF + k0 + gr + 4]);
            }
#pragma unroll
            for (int mt = 0; mt < 4; mt++)
#pragma unroll
                for (int nt = 0; nt < 8; nt++)
                    mma_tf32(acc[mt][nt], af[mt], bf[nt]);
        }
    }

    // ----------------------------- epilogue --------------------------------
#pragma unroll
    for (int mt = 0; mt < 4; mt++) {
        const int r0 = m0 + wm * 64 + mt * 16 + gq;
#pragma unroll
        for (int nt = 0; nt < 8; nt++) {
            const int c0 = n0 + wn * 64 + nt * 8 + gr * 2;
            float b0 = bias[c0], b1 = bias[c0 + 1];
            float v0 = acc[mt][nt][0] + b0;
            float v1 = acc[mt][nt][1] + b1;
            float v2 = acc[mt][nt][2] + b0;
            float v3 = acc[mt][nt][3] + b1;
            if (ACT) {
                v0 = (v0 > 0.f) ? (v0 + 1.f) : expf(v0);
                v1 = (v1 > 0.f) ? (v1 + 1.f) : expf(v1);
                v2 = (v2 > 0.f) ? (v2 + 1.f) : expf(v2);
                v3 = (v3 > 0.f) ? (v3 + 1.f) : expf(v3);
            }
            *(float2*)(C + (size_t)r0 * Dm + c0)       = make_float2(v0, v1);
            *(float2*)(C + (size_t)(r0 + 8) * Dm + c0) = make_float2(v2, v3);
        }
    }
}

// ------------------------------------------------------------ tf32 rounding
__device__ __forceinline__ float rtf32(float x) {
    uint32_t u;
    asm("cvt.rna.tf32.f32 %0, %1;" : "=r"(u) : "f"(x));
    return __uint_as_float(u);
}

__global__ void to_tf32(const float* __restrict__ in, float* __restrict__ out, int n4)
{
    int i = blockIdx.x * 256 + threadIdx.x;
    if (i >= n4) return;
    float4 v = ((const float4*)in)[i];
    v.x = rtf32(v.x); v.y = rtf32(v.y); v.z = rtf32(v.z); v.w = rtf32(v.w);
    ((float4*)out)[i] = v;
}

// ---------------------------------------------------------------- scan stage
__global__ void chunk_partial(const float* __restrict__ pk,
                              const float* __restrict__ pv,
                              float* __restrict__ part)
{
    const int d = blockIdx.x * 256 + threadIdx.x;
    const int c = blockIdx.y;
    const int b = blockIdx.z;
    size_t base = ((size_t)b * Lseq + (size_t)c * CH) * Dm + d;
    float s = 0.f;
#pragma unroll 4
    for (int i = 0; i < CH; i++) {
        size_t idx = base + (size_t)i * Dm;
        s += pk[idx] * pv[idx];
    }
    part[((size_t)b * NC + c) * Dm + d] = s;
}

__global__ void scan_partials(float* __restrict__ part)
{
    const int d = blockIdx.x * 256 + threadIdx.x;
    const int b = blockIdx.y;
    float run = 0.f;
    for (int c = 0; c < NC; c++) {
        size_t idx = ((size_t)b * NC + c) * Dm + d;
        float t = part[idx];
        part[idx] = run;
        run += t;
    }
}

__global__ void apply_scan(const float* __restrict__ pq,
                           const float* __restrict__ pk,
                           const float* __restrict__ pv,
                           const float* __restrict__ part,
                           float* __restrict__ ctx)
{
    const int d = blockIdx.x * 256 + threadIdx.x;
    const int c = blockIdx.y;
    const int b = blockIdx.z;
    float run = part[((size_t)b * NC + c) * Dm + d];
    size_t base = ((size_t)b * Lseq + (size_t)c * CH) * Dm + d;
#pragma unroll 4
    for (int i = 0; i < CH; i++) {
        size_t idx = base + (size_t)i * Dm;
        run += pk[idx] * pv[idx];
        ctx[idx] = rtf32(pq[idx] * run * SCALE);   // rounded: next GEMM input
    }
}

// ---------------------------------------------------------------- launch
extern "C" void kernel_launch(void* const* d_in, const int* in_sizes, int n_in,
                              void* d_out, int out_size)
{
    const float* x  = (const float*)d_in[0];
    const float* Wq = (const float*)d_in[1];
    const float* bq = (const float*)d_in[2];
    const float* Wk = (const float*)d_in[3];
    const float* bk = (const float*)d_in[4];
    const float* Wv = (const float*)d_in[5];
    const float* bv = (const float*)d_in[6];
    const float* Wo = (const float*)d_in[7];
    const float* bo = (const float*)d_in[8];
    float* out = (float*)d_out;

    float *xc, *wc, *phiq, *phik, *v, *ctx, *part;
    cudaGetSymbolAddress((void**)&xc,   g_xc);
    cudaGetSymbolAddress((void**)&wc,   g_wc);
    cudaGetSymbolAddress((void**)&phiq, g_phiq);
    cudaGetSymbolAddress((void**)&phik, g_phik);
    cudaGetSymbolAddress((void**)&v,    g_v);
    cudaGetSymbolAddress((void**)&ctx,  g_ctx);
    cudaGetSymbolAddress((void**)&part, g_part);
    float* wcq = wc;
    float* wck = wc + (size_t)Dm * Dm;
    float* wcv = wc + 2 * (size_t)Dm * Dm;
    float* wco = wc + 3 * (size_t)Dm * Dm;

    static bool attr_set = false;
    if (!attr_set) {
        cudaFuncSetAttribute(gemm_mma<0>, cudaFuncAttributeMaxDynamicSharedMemorySize, SMEM_TOTAL);
        cudaFuncSetAttribute(gemm_mma<1>, cudaFuncAttributeMaxDynamicSharedMemorySize, SMEM_TOTAL);
        attr_set = true;
    }

    // tf32 rounding of GEMM inputs
    const int nX4 = Mtot * Dm / 4, nW4 = Dm * Dm / 4;
    to_tf32<<<(nX4 + 255) / 256, 256>>>(x, xc, nX4);
    to_tf32<<<(nW4 + 255) / 256, 256>>>(Wq, wcq, nW4);
    to_tf32<<<(nW4 + 255) / 256, 256>>>(Wk, wck, nW4);
    to_tf32<<<(nW4 + 255) / 256, 256>>>(Wv, wcv, nW4);
    to_tf32<<<(nW4 + 255) / 256, 256>>>(Wo, wco, nW4);

    dim3 ggrid(Dm / BN, Mtot / BM);   // (8, 128)
    gemm_mma<1><<<ggrid, 256, SMEM_TOTAL>>>(xc, wcq, bq, phiq);
    gemm_mma<1><<<ggrid, 256, SMEM_TOTAL>>>(xc, wck, bk, phik);
    gemm_mma<0><<<ggrid, 256, SMEM_TOTAL>>>(xc, wcv, bv, v);

    dim3 pgrid(Dm / 256, NC, Bz);
    chunk_partial<<<pgrid, 256>>>(phik, v, part);
    dim3 sgrid(Dm / 256, Bz);
    scan_partials<<<sgrid, 256>>>(part);
    apply_scan<<<pgrid, 256>>>(phiq, phik, v, part, ctx);

    gemm_mma<0><<<ggrid, 256, SMEM_TOTAL>>>(ctx, wco, bo, out);
}

// round 7
// speedup vs baseline: 1.1213x; 1.0179x over previous
#include <cuda_runtime.h>
#include <cstdint>
#include <math.h>

// ---------------------------------------------------------------- constants
constexpr int Bz   = 4;
constexpr int Lseq = 4096;
constexpr int Dm   = 2048;
constexpr int Mtot = Bz * Lseq;                 // 16384
constexpr float SCALE = 0.08838834764831845f;   // 128^-0.5

constexpr int NC = 64;                          // scan chunks
constexpr int CH = Lseq / NC;                   // 64

// GEMM tiling: CTA 128x256, 8 warps of 64x64, BK=32, 4-stage cp.async
constexpr int BM = 128, BN = 256, BK = 32;
constexpr int STAGES = 4;
constexpr int KT = Dm / BK;                       // 64
constexpr int ROWF = 36;                          // padded row stride (floats)
constexpr int A_TILE = BM * ROWF * 4;             // 18432
constexpr int B_TILE = BN * ROWF * 4;             // 36864
constexpr int STAGE_BYTES = A_TILE + B_TILE;      // 55296
constexpr int SMEM_TOTAL  = STAGES * STAGE_BYTES; // 221184

// ---------------------------------------------------------------- scratch
__device__ float g_xc  [(size_t)Mtot * Dm];
__device__ float g_wc  [4][(size_t)Dm * Dm];
__device__ float g_phiq[(size_t)Mtot * Dm];
__device__ float g_phik[(size_t)Mtot * Dm];
__device__ float g_v   [(size_t)Mtot * Dm];
__device__ float g_ctx [(size_t)Mtot * Dm];
__device__ float g_part[(size_t)Bz * NC * Dm];

// ---------------------------------------------------------------- helpers
__device__ __forceinline__ uint32_t smem_u32(const void* p) {
    uint32_t a;
    asm("{ .reg .u64 t; cvta.to.shared.u64 t, %1; cvt.u32.u64 %0, t; }"
        : "=r"(a) : "l"(p));
    return a;
}
__device__ __forceinline__ void cp16(uint32_t dst, const void* src) {
    asm volatile("cp.async.cg.shared.global [%0], [%1], 16;"
                 :: "r"(dst), "l"(src) : "memory");
}
__device__ __forceinline__ void mma_tf32(float* d, const uint32_t* a,
                                         const uint32_t* b) {
    asm volatile(
        "mma.sync.aligned.m16n8k8.row.col.f32.tf32.tf32.f32 "
        "{%0,%1,%2,%3}, {%4,%5,%6,%7}, {%8,%9}, {%0,%1,%2,%3};"
        : "+f"(d[0]), "+f"(d[1]), "+f"(d[2]), "+f"(d[3])
        : "r"(a[0]), "r"(a[1]), "r"(a[2]), "r"(a[3]), "r"(b[0]), "r"(b[1]));
}
// ldmatrix x4: four 8x8 b16 tiles == four 8x4 tf32 tiles
__device__ __forceinline__ void ldsm4(uint32_t* r, uint32_t addr) {
    asm volatile("ldmatrix.sync.aligned.m8n8.x4.shared.b16 {%0,%1,%2,%3}, [%4];"
                 : "=r"(r[0]), "=r"(r[1]), "=r"(r[2]), "=r"(r[3]) : "r"(addr));
}

// ------------------------------------------------------------------- GEMM
// C[M][N] = act(A[M][K] @ W[N][K]^T + bias[N]); A,W pre-rounded to tf32.
template<int ACT>
__global__ void __launch_bounds__(256, 1)
gemm_mma(const float* __restrict__ A, const float* __restrict__ W,
         const float* __restrict__ bias, float* __restrict__ C)
{
    extern __shared__ float smem[];
    const uint32_t sb = smem_u32(smem);
    const int tid  = threadIdx.x;
    const int wid  = tid >> 5;
    const int lane = tid & 31;
    const int wm = wid & 1;             // 0..1  -> 64-row slab
    const int wn = wid >> 1;            // 0..3  -> 64-col slab
    const int gq = lane >> 2;           // 0..7
    const int gr = lane & 3;            // 0..3
    const int m0 = blockIdx.y * BM;
    const int n0 = blockIdx.x * BN;

    // per-thread ldmatrix row offsets (bytes, relative to stage base)
    // A fragment (m16k8): tile j = lane>>3; row-group=j&1, col-half=j>>1
    uint32_t offA[4], offB[4];
#pragma unroll
    for (int mt = 0; mt < 4; mt++) {
        int row = wm * 64 + mt * 16 + ((lane >> 3) & 1) * 8 + (lane & 7);
        offA[mt] = (uint32_t)(row * 144 + ((lane >> 4) * 16));
    }
    // B pair (two n8k8 frags): tile j = lane>>3; row-group=j>>1, col-half=j&1
#pragma unroll
    for (int p = 0; p < 4; p++) {
        int row = wn * 64 + p * 16 + (lane >> 4) * 8 + (lane & 7);
        offB[p] = (uint32_t)(row * 144 + (((lane >> 3) & 1) * 16));
    }

    float acc[4][8][4];
#pragma unroll
    for (int i = 0; i < 4; i++)
#pragma unroll
        for (int j = 0; j < 8; j++)
#pragma unroll
            for (int k = 0; k < 4; k++) acc[i][j][k] = 0.f;

    auto issue = [&](int kt) {
        const int s = kt & (STAGES - 1);
        const uint32_t dA = sb + s * STAGE_BYTES;
        const uint32_t dB = dA + A_TILE;
        const float* Ag = A + (size_t)m0 * Dm + kt * BK;
        const float* Wg = W + (size_t)n0 * Dm + kt * BK;
#pragma unroll
        for (int i = 0; i < 4; i++) {       // 128 rows x 8 chunks
            int ch = tid + 256 * i, row = ch >> 3, c4 = ch & 7;
            cp16(dA + row * 144 + c4 * 16, Ag + (size_t)row * Dm + c4 * 4);
        }
#pragma unroll
        for (int i = 0; i < 8; i++) {       // 256 rows x 8 chunks
            int ch = tid + 256 * i, row = ch >> 3, c4 = ch & 7;
            cp16(dB + row * 144 + c4 * 16, Wg + (size_t)row * Dm + c4 * 4);
        }
        asm volatile("cp.async.commit_group;" ::: "memory");
    };

    issue(0);
    issue(1);
    issue(2);

    for (int kt = 0; kt < KT; kt++) {
        const int s = kt & (STAGES - 1);
        asm volatile("cp.async.wait_group 2;" ::: "memory");
        __syncthreads();

        if (kt + 3 < KT) issue(kt + 3);
        else asm volatile("cp.async.commit_group;" ::: "memory");

        const uint32_t aBase = sb + s * STAGE_BYTES;
        const uint32_t bBase = aBase + A_TILE;

#pragma unroll
        for (int ks = 0; ks < 4; ks++) {
            const uint32_t kOfs = ks * 32;   // 8 floats per ks step
            uint32_t af[4][4], bfr[16];
#pragma unroll
            for (int mt = 0; mt < 4; mt++)
                ldsm4(af[mt], aBase + offA[mt] + kOfs);
#pragma unroll
            for (int p = 0; p < 4; p++)
                ldsm4(&bfr[4 * p], bBase + offB[p] + kOfs);
#pragma unroll
            for (int mt = 0; mt < 4; mt++)
#pragma unroll
                for (int nt = 0; nt < 8; nt++)
                    mma_tf32(acc[mt][nt], af[mt], &bfr[2 * nt]);
        }
    }

    // ----------------------------- epilogue --------------------------------
#pragma unroll
    for (int mt = 0; mt < 4; mt++) {
        const int r0 = m0 + wm * 64 + mt * 16 + gq;
#pragma unroll
        for (int nt = 0; nt < 8; nt++) {
            const int c0 = n0 + wn * 64 + nt * 8 + gr * 2;
            float b0 = bias[c0], b1 = bias[c0 + 1];
            float v0 = acc[mt][nt][0] + b0;
            float v1 = acc[mt][nt][1] + b1;
            float v2 = acc[mt][nt][2] + b0;
            float v3 = acc[mt][nt][3] + b1;
            if (ACT) {
                v0 = (v0 > 0.f) ? (v0 + 1.f) : expf(v0);
                v1 = (v1 > 0.f) ? (v1 + 1.f) : expf(v1);
                v2 = (v2 > 0.f) ? (v2 + 1.f) : expf(v2);
                v3 = (v3 > 0.f) ? (v3 + 1.f) : expf(v3);
            }
            *(float2*)(C + (size_t)r0 * Dm + c0)       = make_float2(v0, v1);
            *(float2*)(C + (size_t)(r0 + 8) * Dm + c0) = make_float2(v2, v3);
        }
    }
}

// ------------------------------------------------------------ tf32 rounding
__device__ __forceinline__ float rtf32(float x) {
    uint32_t u;
    asm("cvt.rna.tf32.f32 %0, %1;" : "=r"(u) : "f"(x));
    return __uint_as_float(u);
}

__global__ void to_tf32(const float* __restrict__ in, float* __restrict__ out, int n4)
{
    int i = blockIdx.x * 256 + threadIdx.x;
    if (i >= n4) return;
    float4 v = ((const float4*)in)[i];
    v.x = rtf32(v.x); v.y = rtf32(v.y); v.z = rtf32(v.z); v.w = rtf32(v.w);
    ((float4*)out)[i] = v;
}

// ---------------------------------------------------------------- scan stage
__global__ void chunk_partial(const float* __restrict__ pk,
                              const float* __restrict__ pv,
                              float* __restrict__ part)
{
    const int d = blockIdx.x * 256 + threadIdx.x;
    const int c = blockIdx.y;
    const int b = blockIdx.z;
    size_t base = ((size_t)b * Lseq + (size_t)c * CH) * Dm + d;
    float s = 0.f;
#pragma unroll 4
    for (int i = 0; i < CH; i++) {
        size_t idx = base + (size_t)i * Dm;
        s += pk[idx] * pv[idx];
    }
    part[((size_t)b * NC + c) * Dm + d] = s;
}

__global__ void scan_partials(float* __restrict__ part)
{
    const int d = blockIdx.x * 256 + threadIdx.x;
    const int b = blockIdx.y;
    float run = 0.f;
    for (int c = 0; c < NC; c++) {
        size_t idx = ((size_t)b * NC + c) * Dm + d;
        float t = part[idx];
        part[idx] = run;
        run += t;
    }
}

__global__ void apply_scan(const float* __restrict__ pq,
                           const float* __restrict__ pk,
                           const float* __restrict__ pv,
                           const float* __restrict__ part,
                           float* __restrict__ ctx)
{
    const int d = blockIdx.x * 256 + threadIdx.x;
    const int c = blockIdx.y;
    const int b = blockIdx.z;
    float run = part[((size_t)b * NC + c) * Dm + d];
    size_t base = ((size_t)b * Lseq + (size_t)c * CH) * Dm + d;
#pragma unroll 4
    for (int i = 0; i < CH; i++) {
        size_t idx = base + (size_t)i * Dm;
        run += pk[idx] * pv[idx];
        ctx[idx] = rtf32(pq[idx] * run * SCALE);   // rounded: next GEMM input
    }
}

// ---------------------------------------------------------------- launch
extern "C" void kernel_launch(void* const* d_in, const int* in_sizes, int n_in,
                              void* d_out, int out_size)
{
    const float* x  = (const float*)d_in[0];
    const float* Wq = (const float*)d_in[1];
    const float* bq = (const float*)d_in[2];
    const float* Wk = (const float*)d_in[3];
    const float* bk = (const float*)d_in[4];
    const float* Wv = (const float*)d_in[5];
    const float* bv = (const float*)d_in[6];
    const float* Wo = (const float*)d_in[7];
    const float* bo = (const float*)d_in[8];
    float* out = (float*)d_out;

    float *xc, *wc, *phiq, *phik, *v, *ctx, *part;
    cudaGetSymbolAddress((void**)&xc,   g_xc);
    cudaGetSymbolAddress((void**)&wc,   g_wc);
    cudaGetSymbolAddress((void**)&phiq, g_phiq);
    cudaGetSymbolAddress((void**)&phik, g_phik);
    cudaGetSymbolAddress((void**)&v,    g_v);
    cudaGetSymbolAddress((void**)&ctx,  g_ctx);
    cudaGetSymbolAddress((void**)&part, g_part);
    float* wcq = wc;
    float* wck = wc + (size_t)Dm * Dm;
    float* wcv = wc + 2 * (size_t)Dm * Dm;
    float* wco = wc + 3 * (size_t)Dm * Dm;

    static bool attr_set = false;
    if (!attr_set) {
        cudaFuncSetAttribute(gemm_mma<0>, cudaFuncAttributeMaxDynamicSharedMemorySize, SMEM_TOTAL);
        cudaFuncSetAttribute(gemm_mma<1>, cudaFuncAttributeMaxDynamicSharedMemorySize, SMEM_TOTAL);
        attr_set = true;
    }

    // tf32 rounding of GEMM inputs
    const int nX4 = Mtot * Dm / 4, nW4 = Dm * Dm / 4;
    to_tf32<<<(nX4 + 255) / 256, 256>>>(x, xc, nX4);
    to_tf32<<<(nW4 + 255) / 256, 256>>>(Wq, wcq, nW4);
    to_tf32<<<(nW4 + 255) / 256, 256>>>(Wk, wck, nW4);
    to_tf32<<<(nW4 + 255) / 256, 256>>>(Wv, wcv, nW4);
    to_tf32<<<(nW4 + 255) / 256, 256>>>(Wo, wco, nW4);

    dim3 ggrid(Dm / BN, Mtot / BM);   // (8, 128)
    gemm_mma<1><<<ggrid, 256, SMEM_TOTAL>>>(xc, wcq, bq, phiq);
    gemm_mma<1><<<ggrid, 256, SMEM_TOTAL>>>(xc, wck, bk, phik);
    gemm_mma<0><<<ggrid, 256, SMEM_TOTAL>>>(xc, wcv, bv, v);

    dim3 pgrid(Dm / 256, NC, Bz);
    chunk_partial<<<pgrid, 256>>>(phik, v, part);
    dim3 sgrid(Dm / 256, Bz);
    scan_partials<<<sgrid, 256>>>(part);
    apply_scan<<<pgrid, 256>>>(phiq, phik, v, part, ctx);

    gemm_mma<0><<<ggrid, 256, SMEM_TOTAL>>>(ctx, wco, bo, out);
}